// round 9
// baseline (speedup 1.0000x reference)
#include <cuda_runtime.h>
#include <cuda_bf16.h>
#include <cstdint>

// Problem constants (fixed by the dataset)
#define CLASSES   128
#define M_IN      64      // inner dim (K)
#define N_OUT     32      // outputs per class
#define SPLIT     4       // blocks per class in GEMM kernel
#define MAIN_THREADS  256 // 8 warps
#define WARP_BATCH 16     // samples per warp per pass
#define HIST_THREADS  1024
#define MAX_HIST_BLOCKS 128
#define MAX_N (1 << 17)   // capacity of static scratch (dataset N = 65536)

// packed fp32x2 FMA (sm_103a; only reachable via PTX) — proven in R4
#define FMA2(d, a, b, c) \
    asm("fma.rn.f32x2 %0, %1, %2, %3;" : "=l"(d) : "l"(a), "l"(b), "l"(c))
#define UNPACK2(lo, hi, v) \
    asm("mov.b64 {%0, %1}, %2;" : "=f"(lo), "=f"(hi) : "l"(v))

// ---------------- scratch (no allocations allowed) ----------------
__device__ int g_offsets[CLASSES + 1];
__device__ int g_cursor[CLASSES];
__device__ int g_perm[MAX_N];
__device__ int g_blockcounts[MAX_HIST_BLOCKS * CLASSES];
__device__ float g_xsorted[(size_t)MAX_N * M_IN];   // 32MB gathered x rows

// Detect whether the index buffer is int64 or int32.
// If int64 with small class values, every odd int32 word (LE high half) is 0.
__device__ __forceinline__ void detect_is64(const int* w, int nwords, int tid,
                                            int* flag) {
    if (tid < 32) {
        int idx = 2 * tid + 1;
        int v = (idx < nwords) ? w[idx] : 0;
        unsigned nz = __ballot_sync(0xFFFFFFFFu, v != 0);
        if (tid == 0) *flag = (nz == 0u) ? 1 : 0;
    }
}

__device__ __forceinline__ int load_class(const void* inds, int n, int is64) {
    int c;
    if (is64) c = (int)((const long long*)inds)[n];
    else      c = ((const int*)inds)[n];
    return c & (CLASSES - 1);   // defensive clamp
}

// ---------------- kernel 1: per-block histogram ----------------
__global__ void hist_kernel(const void* __restrict__ inds, int N) {
    __shared__ int s_cnt[CLASSES];
    __shared__ int s_is64;
    int t = threadIdx.x;
    if (t < CLASSES) s_cnt[t] = 0;
    detect_is64((const int*)inds, N, t, &s_is64);
    __syncthreads();
    for (int n = blockIdx.x * HIST_THREADS + t; n < N;
         n += gridDim.x * HIST_THREADS)
        atomicAdd(&s_cnt[load_class(inds, n, s_is64)], 1);
    __syncthreads();
    if (t < CLASSES) g_blockcounts[blockIdx.x * CLASSES + t] = s_cnt[t];
}

// ---------------- kernel 2: reduce + exclusive scan ----------------
__global__ void scan_kernel(int nblocks) {
    __shared__ int s[CLASSES];
    int t = threadIdx.x;   // 128 threads
    int sum = 0;
    for (int b = 0; b < nblocks; b++)
        sum += g_blockcounts[b * CLASSES + t];
    s[t] = sum;
    __syncthreads();
    #pragma unroll
    for (int off = 1; off < CLASSES; off <<= 1) {
        int v = (t >= off) ? s[t - off] : 0;
        __syncthreads();
        s[t] += v;
        __syncthreads();
    }
    int incl = s[t];
    g_offsets[t + 1] = incl;
    if (t == 0) g_offsets[0] = 0;
    g_cursor[t] = incl - sum;   // exclusive prefix
}

// ---------------- kernel 3: scatter + fused x gather ----------------
// Computes each sample's destination slot (two-level atomics, proven) and
// warp-cooperatively copies x[n] -> g_xsorted[slot]. Reads coalesced
// (consecutive n), writes 256B-contiguous rows. Pure streaming kernel.
__global__ void scatter_gather_kernel(const void* __restrict__ inds,
                                      const float* __restrict__ x, int N) {
    __shared__ int s_cnt[CLASSES];
    __shared__ int s_base[CLASSES];
    __shared__ int s_is64;
    int t = threadIdx.x;
    int lane = t & 31;
    if (t < CLASSES) s_cnt[t] = 0;
    detect_is64((const int*)inds, N, t, &s_is64);
    __syncthreads();
    int n = blockIdx.x * HIST_THREADS + t;
    int c = 0, loc = 0;
    bool valid = n < N;
    if (valid) {
        c = load_class(inds, n, s_is64);
        loc = atomicAdd(&s_cnt[c], 1);
    }
    __syncthreads();
    if (t < CLASSES) s_base[t] = atomicAdd(&g_cursor[t], s_cnt[t]);
    __syncthreads();
    int slot = 0;
    if (valid) {
        slot = s_base[c] + loc;
        g_perm[slot] = n;
    }

    // warp-cooperative row copy: 2 rows per step (lanes 0-15 / 16-31)
    unsigned vmask = __ballot_sync(0xFFFFFFFFu, valid);
    #pragma unroll 4
    for (int r = 0; r < 32; r += 2) {
        int nA  = __shfl_sync(0xFFFFFFFFu, n, r);
        int slA = __shfl_sync(0xFFFFFFFFu, slot, r);
        int nB  = __shfl_sync(0xFFFFFFFFu, n, r + 1);
        int slB = __shfl_sync(0xFFFFFFFFu, slot, r + 1);
        bool vA = (vmask >> r) & 1u;
        bool vB = (vmask >> (r + 1)) & 1u;
        int  myn = (lane < 16) ? nA : nB;
        int  mys = (lane < 16) ? slA : slB;
        bool myv = (lane < 16) ? vA : vB;
        if (myv) {
            const float4* s = reinterpret_cast<const float4*>(x + (size_t)myn * M_IN);
            float4* d = reinterpret_cast<float4*>(g_xsorted + (size_t)mys * M_IN);
            d[lane & 15] = s[lane & 15];
        }
    }
}

// ---------------- kernel 4: GEMM over sorted x ----------------
// grid = CLASSES * SPLIT blocks, 256 threads (8 warps).
// x_sorted is read CONTIGUOUSLY (no indirection on the load path); perm is
// needed only for the scattered output stores. Compute = R8 batch structure
// with R4's FFMA2 inner loop (k-even/odd packed partials).
__global__ void __launch_bounds__(MAIN_THREADS, 4)
main_kernel(const float* __restrict__ W,
            const float* __restrict__ b,
            float* __restrict__ out) {
    __shared__ float W_sh[N_OUT * 68];          // padded rows: stride 68 floats
    __shared__ float b_sh[N_OUT];
    __shared__ float x_sh[8][WARP_BATCH][M_IN]; // [warp][sample][k]  32KB
    __shared__ int   n_idx[8][WARP_BATCH];

    const int tid  = threadIdx.x;
    const int w    = tid >> 5;
    const int lane = tid & 31;

    const int c = blockIdx.x / SPLIT;
    const int q = blockIdx.x % SPLIT;

    const int start = g_offsets[c];
    const int endc  = g_offsets[c + 1];
    const int total = endc - start;
    const int chunk = (total + SPLIT - 1) / SPLIT;
    const int s0 = start + q * chunk;
    const int s1 = min(endc, s0 + chunk);

    // ---- stage W slice (2048 floats) as float4, padded rows
    const float4* Wg = reinterpret_cast<const float4*>(W + (size_t)c * (N_OUT * M_IN));
    #pragma unroll
    for (int i = 0; i < 2; i++) {
        int idx = tid + i * MAIN_THREADS;           // 0..511 float4s
        float4 v = Wg[idx];
        *reinterpret_cast<float4*>(&W_sh[(idx >> 4) * 68 + (idx & 15) * 4]) = v;
    }
    if (tid < N_OUT) b_sh[tid] = b[c * N_OUT + tid];
    __syncthreads();

    const float bias = b_sh[lane];

    for (int base = s0 + w * WARP_BATCH; base < s1; base += 8 * WARP_BATCH) {
        int rem = s1 - base; if (rem > WARP_BATCH) rem = WARP_BATCH;

        // perm ids (store path only)
        if (lane < WARP_BATCH)
            n_idx[w][lane] = g_perm[base + (lane < rem ? lane : rem - 1)];

        // ---- contiguous x_sorted tile load: 16 rows x 16 float4,
        //      8 LDG.128 per lane, all independent (front-batched).
        float4 r[8];
        #pragma unroll
        for (int i = 0; i < 8; i++) {
            int t2  = lane + 32 * i;                 // 0..255
            int row = t2 >> 4;
            int kp  = t2 & 15;
            int gr  = base + row; if (gr > s1 - 1) gr = s1 - 1;
            r[i] = *reinterpret_cast<const float4*>(
                g_xsorted + (size_t)gr * M_IN + kp * 4);
        }
        #pragma unroll
        for (int i = 0; i < 8; i++) {
            int t2  = lane + 32 * i;
            *reinterpret_cast<float4*>(&x_sh[w][t2 >> 4][(t2 & 15) * 4]) = r[i];
        }
        __syncwarp();

        // ---- two 8-sample FFMA2 passes (k-even/odd packed partials)
        #pragma unroll
        for (int half = 0; half < 2; half++) {
            unsigned long long acc[8];
            #pragma unroll
            for (int s = 0; s < 8; s++) acc[s] = 0ull;

            const ulonglong2* wrow =
                reinterpret_cast<const ulonglong2*>(&W_sh[lane * 68]);
            #pragma unroll
            for (int k4 = 0; k4 < 16; k4++) {
                ulonglong2 wv = wrow[k4];
                #pragma unroll
                for (int s = 0; s < 8; s++) {
                    ulonglong2 xv = *reinterpret_cast<const ulonglong2*>(
                        &x_sh[w][half * 8 + s][k4 * 4]);
                    FMA2(acc[s], wv.x, xv.x, acc[s]);
                    FMA2(acc[s], wv.y, xv.y, acc[s]);
                }
            }
            #pragma unroll
            for (int s = 0; s < 8; s++) {
                int gs = half * 8 + s;
                if (gs < rem) {
                    int n = n_idx[w][gs];
                    float lo, hi;
                    UNPACK2(lo, hi, acc[s]);
                    out[(size_t)n * N_OUT + lane] = lo + hi + bias;
                }
            }
        }
        __syncwarp();   // lanes done with x_sh before next pass overwrite
    }
}

// ---------------- launch ----------------
extern "C" void kernel_launch(void* const* d_in, const int* in_sizes, int n_in,
                              void* d_out, int out_size) {
    const float* x    = (const float*)d_in[0];
    const void*  inds = d_in[1];
    const float* W    = (const float*)d_in[2];
    const float* b    = (const float*)d_in[3];
    float*       out  = (float*)d_out;
    const int N = in_sizes[1];

    int hist_blocks = (N + HIST_THREADS - 1) / HIST_THREADS;
    if (hist_blocks > MAX_HIST_BLOCKS) hist_blocks = MAX_HIST_BLOCKS;
    hist_kernel<<<hist_blocks, HIST_THREADS>>>(inds, N);
    scan_kernel<<<1, CLASSES>>>(hist_blocks);
    int sg_blocks = (N + HIST_THREADS - 1) / HIST_THREADS;
    scatter_gather_kernel<<<sg_blocks, HIST_THREADS>>>(inds, x, N);
    main_kernel<<<CLASSES * SPLIT, MAIN_THREADS>>>(W, b, out);
}

// round 10
// speedup vs baseline: 1.1566x; 1.1566x over previous
#include <cuda_runtime.h>
#include <cuda_bf16.h>
#include <cstdint>

// Problem constants (fixed by the dataset)
#define CLASSES   128
#define M_IN      64      // inner dim (K)
#define N_OUT     32      // outputs per class
#define SPLIT     4       // blocks per class in main kernel
#define MAIN_THREADS  256 // 8 warps
#define WARP_BATCH 16     // samples per warp per pass
#define HIST_THREADS  1024
#define MAX_HIST_BLOCKS 1024

// ---------------- scratch (no allocations allowed) ----------------
__device__ int g_offsets[CLASSES + 1];
__device__ int g_cursor[CLASSES];
__device__ int g_perm[1 << 20];           // supports up to 1M samples
__device__ int g_blockcounts[MAX_HIST_BLOCKS * CLASSES];

// Detect whether the index buffer is int64 or int32.
// If int64 with small class values, every odd int32 word (LE high half) is 0.
__device__ __forceinline__ void detect_is64(const int* w, int nwords, int tid,
                                            int* flag) {
    if (tid < 32) {
        int idx = 2 * tid + 1;
        int v = (idx < nwords) ? w[idx] : 0;
        unsigned nz = __ballot_sync(0xFFFFFFFFu, v != 0);
        if (tid == 0) *flag = (nz == 0u) ? 1 : 0;
    }
}

__device__ __forceinline__ int load_class(const void* inds, int n, int is64) {
    int c;
    if (is64) c = (int)((const long long*)inds)[n];
    else      c = ((const int*)inds)[n];
    return c & (CLASSES - 1);   // defensive clamp
}

// ---------------- kernel 1: per-block histogram ----------------
__global__ void hist_kernel(const void* __restrict__ inds, int N) {
    __shared__ int s_cnt[CLASSES];
    __shared__ int s_is64;
    int t = threadIdx.x;
    if (t < CLASSES) s_cnt[t] = 0;
    detect_is64((const int*)inds, N, t, &s_is64);
    __syncthreads();
    int n = blockIdx.x * HIST_THREADS + t;
    if (n < N) atomicAdd(&s_cnt[load_class(inds, n, s_is64)], 1);
    __syncthreads();
    if (t < CLASSES) g_blockcounts[blockIdx.x * CLASSES + t] = s_cnt[t];
}

// ---------------- kernel 2: reduce + exclusive scan ----------------
__global__ void scan_kernel(int nblocks) {
    __shared__ int s[CLASSES];
    int t = threadIdx.x;   // 128 threads
    int sum = 0;
    for (int b = 0; b < nblocks; b++)
        sum += g_blockcounts[b * CLASSES + t];
    s[t] = sum;
    __syncthreads();
    #pragma unroll
    for (int off = 1; off < CLASSES; off <<= 1) {
        int v = (t >= off) ? s[t - off] : 0;
        __syncthreads();
        s[t] += v;
        __syncthreads();
    }
    int incl = s[t];
    g_offsets[t + 1] = incl;
    if (t == 0) g_offsets[0] = 0;
    g_cursor[t] = incl - sum;   // exclusive prefix
}

// ---------------- kernel 3: scatter (two-level) ----------------
__global__ void scatter_kernel(const void* __restrict__ inds, int N) {
    __shared__ int s_cnt[CLASSES];
    __shared__ int s_base[CLASSES];
    __shared__ int s_is64;
    int t = threadIdx.x;
    if (t < CLASSES) s_cnt[t] = 0;
    detect_is64((const int*)inds, N, t, &s_is64);
    __syncthreads();
    int n = blockIdx.x * HIST_THREADS + t;
    int c = 0, loc = 0;
    if (n < N) {
        c = load_class(inds, n, s_is64);
        loc = atomicAdd(&s_cnt[c], 1);
    }
    __syncthreads();
    if (t < CLASSES) s_base[t] = atomicAdd(&g_cursor[t], s_cnt[t]);
    __syncthreads();
    if (n < N) g_perm[s_base[c] + loc] = n;
}

// ---------------- kernel 4: main gathered GEMV (clean inner loop) -------
// grid = CLASSES * SPLIT blocks, 256 threads (8 warps), 4 CTAs/SM.
// Warp handles 16 samples per pass: front-batched x gather (8 independent
// LDG.128/lane), then two 8-sample FFMA passes. Inner loop uses a plain
// constant-indexed register array -> pure FFMA + LDS in SASS (no SEL/MOV
// selection chains, which were ~60% of the issued stream in prior rounds).
__global__ void __launch_bounds__(MAIN_THREADS, 4)
main_kernel(const float* __restrict__ x,
            const float* __restrict__ W,
            const float* __restrict__ b,
            float* __restrict__ out) {
    __shared__ float W_sh[N_OUT * 68];          // padded rows: stride 68 floats
    __shared__ float b_sh[N_OUT];
    __shared__ float x_sh[8][WARP_BATCH][M_IN]; // [warp][sample][k]  32KB
    __shared__ int   n_idx[8][WARP_BATCH];

    const int tid  = threadIdx.x;
    const int w    = tid >> 5;
    const int lane = tid & 31;

    const int c = blockIdx.x / SPLIT;
    const int q = blockIdx.x % SPLIT;

    const int start = g_offsets[c];
    const int endc  = g_offsets[c + 1];
    const int total = endc - start;
    const int chunk = (total + SPLIT - 1) / SPLIT;
    const int s0 = start + q * chunk;
    const int s1 = min(endc, s0 + chunk);

    int base = s0 + w * WARP_BATCH;

    // prologue: perm ids for pass 0 before W staging (overlap DRAM chains)
    if (lane < WARP_BATCH && base < s1) {
        int rem0 = s1 - base; if (rem0 > WARP_BATCH) rem0 = WARP_BATCH;
        n_idx[w][lane] = g_perm[base + (lane < rem0 ? lane : rem0 - 1)];
    }

    // stage W slice (2048 floats) as float4, padded rows
    const float4* Wg = reinterpret_cast<const float4*>(W + (size_t)c * (N_OUT * M_IN));
    #pragma unroll
    for (int i = 0; i < 2; i++) {
        int idx = tid + i * MAIN_THREADS;           // 0..511 float4s
        float4 v = Wg[idx];
        *reinterpret_cast<float4*>(&W_sh[(idx >> 4) * 68 + (idx & 15) * 4]) = v;
    }
    if (tid < N_OUT) b_sh[tid] = b[c * N_OUT + tid];
    __syncthreads();

    const float bias = b_sh[lane];

    for (; base < s1; base += 8 * WARP_BATCH) {
        int rem = s1 - base; if (rem > WARP_BATCH) rem = WARP_BATCH;

        if (base != s0 + w * WARP_BATCH) {          // pass>0: reload ids
            if (lane < WARP_BATCH)
                n_idx[w][lane] = g_perm[base + (lane < rem ? lane : rem - 1)];
        }
        __syncwarp();

        // front-batched x gather: 16 rows x 16 float4 = 256 float4,
        // 8 per lane, all issued before any STS (MLP=8/lane).
        float4 r[8];
        #pragma unroll
        for (int i = 0; i < 8; i++) {
            int t2  = lane + 32 * i;                // 0..255
            int row = t2 >> 4;
            int kp  = t2 & 15;
            int n   = n_idx[w][row];
            r[i] = *reinterpret_cast<const float4*>(x + (size_t)n * M_IN + kp * 4);
        }
        #pragma unroll
        for (int i = 0; i < 8; i++) {
            int t2  = lane + 32 * i;
            *reinterpret_cast<float4*>(&x_sh[w][t2 >> 4][(t2 & 15) * 4]) = r[i];
        }
        __syncwarp();

        // two 8-sample compute passes, clean register-array accumulators
        #pragma unroll
        for (int half = 0; half < 2; half++) {
            float acc[8];
            #pragma unroll
            for (int s = 0; s < 8; s++) acc[s] = 0.f;

            const float* wrow = &W_sh[lane * 68];
            #pragma unroll
            for (int k4 = 0; k4 < 16; k4++) {
                float4 wv = *reinterpret_cast<const float4*>(wrow + k4 * 4);
                #pragma unroll
                for (int s = 0; s < 8; s++) {
                    float4 xv = *reinterpret_cast<const float4*>(
                        &x_sh[w][half * 8 + s][k4 * 4]);
                    acc[s] = fmaf(wv.x, xv.x, acc[s]);
                    acc[s] = fmaf(wv.y, xv.y, acc[s]);
                    acc[s] = fmaf(wv.z, xv.z, acc[s]);
                    acc[s] = fmaf(wv.w, xv.w, acc[s]);
                }
            }
            #pragma unroll
            for (int s = 0; s < 8; s++) {
                int gs = half * 8 + s;
                if (gs < rem) {
                    int n = n_idx[w][gs];
                    out[(size_t)n * N_OUT + lane] = acc[s] + bias;
                }
            }
        }
        __syncwarp();   // lanes done with x_sh before next pass overwrite
    }
}

// ---------------- launch ----------------
extern "C" void kernel_launch(void* const* d_in, const int* in_sizes, int n_in,
                              void* d_out, int out_size) {
    const float* x    = (const float*)d_in[0];
    const void*  inds = d_in[1];
    const float* W    = (const float*)d_in[2];
    const float* b    = (const float*)d_in[3];
    float*       out  = (float*)d_out;
    const int N = in_sizes[1];

    int hist_blocks = (N + HIST_THREADS - 1) / HIST_THREADS;
    if (hist_blocks > MAX_HIST_BLOCKS) hist_blocks = MAX_HIST_BLOCKS;
    hist_kernel<<<hist_blocks, HIST_THREADS>>>(inds, N);
    scan_kernel<<<1, CLASSES>>>(hist_blocks);
    scatter_kernel<<<hist_blocks, HIST_THREADS>>>(inds, N);
    main_kernel<<<CLASSES * SPLIT, MAIN_THREADS>>>(x, W, b, out);
}

// round 12
// speedup vs baseline: 1.7203x; 1.4873x over previous
#include <cuda_runtime.h>
#include <cuda_bf16.h>
#include <cstdint>

// Problem constants (fixed by the dataset)
#define CLASSES   128
#define M_IN      64      // K dim
#define N_OUT     32      // outputs per class
#define SPLIT     4       // blocks per class
#define TILE_M    128     // samples per tile (block)
#define TC_THREADS 128    // 4 warps
#define HIST_THREADS  1024
#define MAX_HIST_BLOCKS 1024
#define XPITCH 36         // uint32 pitch of pair arrays (conflict-free + 8B aligned)

// ---------------- scratch (no allocations allowed) ----------------
__device__ int g_offsets[CLASSES + 1];
__device__ int g_cursor[CLASSES];
__device__ int g_perm[1 << 20];
__device__ int g_blockcounts[MAX_HIST_BLOCKS * CLASSES];

// bf16 hi/lo split of two floats -> packed bf16x2 words (x in LOW half)
__device__ __forceinline__ void split2(float x, float y,
                                       uint32_t& hi, uint32_t& lo) {
    asm("cvt.rn.satfinite.bf16x2.f32 %0, %1, %2;" : "=r"(hi) : "f"(y), "f"(x));
    float hx = __uint_as_float(hi << 16);
    float hy = __uint_as_float(hi & 0xFFFF0000u);
    float lx = x - hx, ly = y - hy;
    asm("cvt.rn.satfinite.bf16x2.f32 %0, %1, %2;" : "=r"(lo) : "f"(ly), "f"(lx));
}

// warp-level bf16 MMA: D[16,8] += A[16,16] * B[16,8]  (f32 accumulate)
__device__ __forceinline__ void mma16816(float* d, uint32_t a0, uint32_t a1,
                                         uint32_t a2, uint32_t a3,
                                         uint32_t b0, uint32_t b1) {
    asm volatile(
        "mma.sync.aligned.m16n8k16.row.col.f32.bf16.bf16.f32 "
        "{%0,%1,%2,%3}, {%4,%5,%6,%7}, {%8,%9}, {%0,%1,%2,%3};"
        : "+f"(d[0]), "+f"(d[1]), "+f"(d[2]), "+f"(d[3])
        : "r"(a0), "r"(a1), "r"(a2), "r"(a3), "r"(b0), "r"(b1));
}

// ================= sort pipeline (proven) =================
__device__ __forceinline__ void detect_is64(const int* w, int nwords, int tid,
                                            int* flag) {
    if (tid < 32) {
        int idx = 2 * tid + 1;
        int v = (idx < nwords) ? w[idx] : 0;
        unsigned nz = __ballot_sync(0xFFFFFFFFu, v != 0);
        if (tid == 0) *flag = (nz == 0u) ? 1 : 0;
    }
}
__device__ __forceinline__ int load_class(const void* inds, int n, int is64) {
    int c;
    if (is64) c = (int)((const long long*)inds)[n];
    else      c = ((const int*)inds)[n];
    return c & (CLASSES - 1);
}

__global__ void hist_kernel(const void* __restrict__ inds, int N) {
    __shared__ int s_cnt[CLASSES];
    __shared__ int s_is64;
    int t = threadIdx.x;
    if (t < CLASSES) s_cnt[t] = 0;
    detect_is64((const int*)inds, N, t, &s_is64);
    __syncthreads();
    int n = blockIdx.x * HIST_THREADS + t;
    if (n < N) atomicAdd(&s_cnt[load_class(inds, n, s_is64)], 1);
    __syncthreads();
    if (t < CLASSES) g_blockcounts[blockIdx.x * CLASSES + t] = s_cnt[t];
}

__global__ void scan_kernel(int nblocks) {
    __shared__ int s[CLASSES];
    int t = threadIdx.x;
    int sum = 0;
    for (int b = 0; b < nblocks; b++) sum += g_blockcounts[b * CLASSES + t];
    s[t] = sum;
    __syncthreads();
    #pragma unroll
    for (int off = 1; off < CLASSES; off <<= 1) {
        int v = (t >= off) ? s[t - off] : 0;
        __syncthreads();
        s[t] += v;
        __syncthreads();
    }
    int incl = s[t];
    g_offsets[t + 1] = incl;
    if (t == 0) g_offsets[0] = 0;
    g_cursor[t] = incl - sum;
}

__global__ void scatter_kernel(const void* __restrict__ inds, int N) {
    __shared__ int s_cnt[CLASSES];
    __shared__ int s_base[CLASSES];
    __shared__ int s_is64;
    int t = threadIdx.x;
    if (t < CLASSES) s_cnt[t] = 0;
    detect_is64((const int*)inds, N, t, &s_is64);
    __syncthreads();
    int n = blockIdx.x * HIST_THREADS + t;
    int c = 0, loc = 0;
    if (n < N) {
        c = load_class(inds, n, s_is64);
        loc = atomicAdd(&s_cnt[c], 1);
    }
    __syncthreads();
    if (t < CLASSES) s_base[t] = atomicAdd(&g_cursor[t], s_cnt[t]);
    __syncthreads();
    if (n < N) g_perm[s_base[c] + loc] = n;
}

// ================= main kernel: bf16 hi/lo mma.sync =================
// grid = CLASSES*SPLIT, 128 threads (4 warps). Block (c,q) handles tiles
// q, q+4, ... of class c: D[128,32] = x_tile[128,64] * W_c[32,64]^T + b.
// fp32 split into bf16 hi+lo; 3 MMA terms (hh + hl + lh), f32 accumulate.
__global__ void __launch_bounds__(TC_THREADS, 4)
main_kernel(const float* __restrict__ x,
            const float* __restrict__ W,
            const float* __restrict__ b,
            float* __restrict__ out) {
    // pair arrays: element = packed bf16x2 (k even in low, k odd in high)
    __shared__ uint32_t x_hi[TILE_M][XPITCH];   // 18KB
    __shared__ uint32_t x_lo[TILE_M][XPITCH];   // 18KB
    __shared__ uint32_t w_hi[N_OUT][XPITCH];    // 4.5KB
    __shared__ uint32_t w_lo[N_OUT][XPITCH];    // 4.5KB
    __shared__ float    bias_sh[N_OUT];
    __shared__ int      n_idx[TILE_M];

    const int tid  = threadIdx.x;
    const int w    = tid >> 5;
    const int lane = tid & 31;

    const int c = blockIdx.x >> 2;              // SPLIT = 4
    const int q = blockIdx.x & 3;

    const int c_start = g_offsets[c];
    const int c_end   = g_offsets[c + 1];
    const int ts0 = c_start + q * TILE_M;
    if (ts0 >= c_end) return;                   // uniform block exit

    // ---- W conversion (once): 512 float4 / 128 threads = 4 each ----
    const float4* Wg = reinterpret_cast<const float4*>(W + (size_t)c * (N_OUT * M_IN));
    #pragma unroll
    for (int i = 0; i < 4; i++) {
        int idx4 = tid + i * TC_THREADS;        // 0..511
        float4 v = Wg[idx4];
        int j  = idx4 >> 4;                     // W row 0..31
        int k4 = idx4 & 15;                     // float4 index in row
        uint32_t h0, l0, h1, l1;
        split2(v.x, v.y, h0, l0);
        split2(v.z, v.w, h1, l1);
        *reinterpret_cast<uint2*>(&w_hi[j][2 * k4]) = make_uint2(h0, h1);
        *reinterpret_cast<uint2*>(&w_lo[j][2 * k4]) = make_uint2(l0, l1);
    }
    if (tid < N_OUT) bias_sh[tid] = b[c * N_OUT + tid];

    for (int ts = ts0; ts < c_end; ts += SPLIT * TILE_M) {
        const int rem = min(c_end - ts, TILE_M);

        // ---- x gather + convert: thread = tile row (clamped duplicate) ----
        {
            const int gi = ts + (tid < rem ? tid : rem - 1);
            const int n  = g_perm[gi];
            n_idx[tid] = n;
            const float4* xr = reinterpret_cast<const float4*>(x + (size_t)n * M_IN);
            #pragma unroll
            for (int h = 0; h < 2; h++) {
                float4 v[8];
                #pragma unroll
                for (int i = 0; i < 8; i++) v[i] = xr[h * 8 + i];   // MLP=8
                #pragma unroll
                for (int i = 0; i < 8; i++) {
                    uint32_t h0, l0, h1, l1;
                    split2(v[i].x, v[i].y, h0, l0);
                    split2(v[i].z, v[i].w, h1, l1);
                    int p = 2 * (h * 8 + i);
                    *reinterpret_cast<uint2*>(&x_hi[tid][p]) = make_uint2(h0, h1);
                    *reinterpret_cast<uint2*>(&x_lo[tid][p]) = make_uint2(l0, l1);
                }
            }
        }
        __syncthreads();

        // ---- MMA phase: warp w owns rows [w*32, w*32+32) = 2 m-tiles ----
        float d[2][4][4];
        #pragma unroll
        for (int mt = 0; mt < 2; mt++)
            #pragma unroll
            for (int nt = 0; nt < 4; nt++)
                #pragma unroll
                for (int i = 0; i < 4; i++) d[mt][nt][i] = 0.f;

        const int rA = w * 32 + (lane >> 2);    // A-frag base row (mt0)
        const int nB = lane >> 2;               // B-frag col within n-tile
        const int cp = lane & 3;                // pair column within fragment

        #pragma unroll
        for (int ks = 0; ks < 4; ks++) {        // K slices of 16
            const int p0 = ks * 8 + cp;
            const int p4 = p0 + 4;

            uint32_t Ah[8], Bh[8], T[8];
            #pragma unroll
            for (int mt = 0; mt < 2; mt++) {
                int r = rA + mt * 16;
                Ah[mt*4+0] = x_hi[r    ][p0];
                Ah[mt*4+1] = x_hi[r + 8][p0];
                Ah[mt*4+2] = x_hi[r    ][p4];
                Ah[mt*4+3] = x_hi[r + 8][p4];
            }
            #pragma unroll
            for (int nt = 0; nt < 4; nt++) {
                Bh[nt*2+0] = w_hi[nt*8 + nB][p0];
                Bh[nt*2+1] = w_hi[nt*8 + nB][p4];
            }
            #pragma unroll
            for (int mt = 0; mt < 2; mt++)
                #pragma unroll
                for (int nt = 0; nt < 4; nt++)
                    mma16816(d[mt][nt], Ah[mt*4], Ah[mt*4+1], Ah[mt*4+2],
                             Ah[mt*4+3], Bh[nt*2], Bh[nt*2+1]);

            // term 2: A_hi * B_lo
            #pragma unroll
            for (int nt = 0; nt < 4; nt++) {
                T[nt*2+0] = w_lo[nt*8 + nB][p0];
                T[nt*2+1] = w_lo[nt*8 + nB][p4];
            }
            #pragma unroll
            for (int mt = 0; mt < 2; mt++)
                #pragma unroll
                for (int nt = 0; nt < 4; nt++)
                    mma16816(d[mt][nt], Ah[mt*4], Ah[mt*4+1], Ah[mt*4+2],
                             Ah[mt*4+3], T[nt*2], T[nt*2+1]);

            // term 3: A_lo * B_hi
            #pragma unroll
            for (int mt = 0; mt < 2; mt++) {
                int r = rA + mt * 16;
                T[mt*4+0] = x_lo[r    ][p0];
                T[mt*4+1] = x_lo[r + 8][p0];
                T[mt*4+2] = x_lo[r    ][p4];
                T[mt*4+3] = x_lo[r + 8][p4];
            }
            #pragma unroll
            for (int mt = 0; mt < 2; mt++)
                #pragma unroll
                for (int nt = 0; nt < 4; nt++)
                    mma16816(d[mt][nt], T[mt*4], T[mt*4+1], T[mt*4+2],
                             T[mt*4+3], Bh[nt*2], Bh[nt*2+1]);
        }

        // ---- epilogue: bias + scattered row stores (f32x2) ----
        // lane l holds (row l/4, cols 2c,2c+1) and (row l/4+8, same cols).
        #pragma unroll
        for (int mt = 0; mt < 2; mt++) {
            const int r0 = w * 32 + mt * 16 + (lane >> 2);
            const int s0i = n_idx[r0];
            const int s1i = n_idx[r0 + 8];
            #pragma unroll
            for (int nt = 0; nt < 4; nt++) {
                const int col = nt * 8 + cp * 2;
                float2 bp = *reinterpret_cast<const float2*>(&bias_sh[col]);
                float2 v0 = make_float2(d[mt][nt][0] + bp.x, d[mt][nt][1] + bp.y);
                float2 v1 = make_float2(d[mt][nt][2] + bp.x, d[mt][nt][3] + bp.y);
                *reinterpret_cast<float2*>(out + (size_t)s0i * N_OUT + col) = v0;
                *reinterpret_cast<float2*>(out + (size_t)s1i * N_OUT + col) = v1;
            }
        }
        __syncthreads();   // protect shared tiles before next iteration
    }
}

// ---------------- launch ----------------
extern "C" void kernel_launch(void* const* d_in, const int* in_sizes, int n_in,
                              void* d_out, int out_size) {
    const float* x    = (const float*)d_in[0];
    const void*  inds = d_in[1];
    const float* W    = (const float*)d_in[2];
    const float* b    = (const float*)d_in[3];
    float*       out  = (float*)d_out;
    const int N = in_sizes[1];

    int hist_blocks = (N + HIST_THREADS - 1) / HIST_THREADS;
    if (hist_blocks > MAX_HIST_BLOCKS) hist_blocks = MAX_HIST_BLOCKS;
    hist_kernel<<<hist_blocks, HIST_THREADS>>>(inds, N);
    scan_kernel<<<1, CLASSES>>>(hist_blocks);
    scatter_kernel<<<hist_blocks, HIST_THREADS>>>(inds, N);
    main_kernel<<<CLASSES * SPLIT, TC_THREADS>>>(x, W, b, out);
}